// round 1
// baseline (speedup 1.0000x reference)
#include <cuda_runtime.h>
#include <math.h>

#define FFT_N   4096
#define NTHREADS 512
#define PADSTRIDE 4224            // 4096 + 4096/32
#define PAD(i) ((i) + ((i) >> 5))

// Twiddle table: d_tw[j] = exp(-2*pi*i * j / 4096)
__device__ float2 d_tw[FFT_N];

__global__ void tw_init_kernel() {
    int j = blockIdx.x * blockDim.x + threadIdx.x;
    if (j < FFT_N) {
        double ang = -2.0 * 3.14159265358979323846 * (double)j / (double)FFT_N;
        d_tw[j] = make_float2((float)cos(ang), (float)sin(ang));
    }
}

__device__ __forceinline__ float2 cadd(float2 a, float2 b) { return make_float2(a.x + b.x, a.y + b.y); }
__device__ __forceinline__ float2 csub(float2 a, float2 b) { return make_float2(a.x - b.x, a.y - b.y); }
__device__ __forceinline__ float2 cmul(float2 a, float2 b) {
    return make_float2(fmaf(a.x, b.x, -a.y * b.y), fmaf(a.x, b.y, a.y * b.x));
}
// multiply by -i (DIR=-1, forward) or +i (DIR=+1, inverse)
template <int DIR>
__device__ __forceinline__ float2 rotI(float2 z) {
    return (DIR < 0) ? make_float2(z.y, -z.x) : make_float2(-z.y, z.x);
}

// In-register 8-point DFT (DIT: two DFT4s + W8 combine). DIR=-1 fwd, +1 inv (unnormalized).
template <int DIR>
__device__ __forceinline__ void dft8(float2 v[8]) {
    const float h = 0.70710678118654752f;
    float2 t0 = cadd(v[0], v[4]), t1 = csub(v[0], v[4]);
    float2 t2 = cadd(v[2], v[6]), t3 = csub(v[2], v[6]);
    float2 u0 = cadd(v[1], v[5]), u1 = csub(v[1], v[5]);
    float2 u2 = cadd(v[3], v[7]), u3 = csub(v[3], v[7]);
    float2 e0 = cadd(t0, t2), e2 = csub(t0, t2);
    float2 rt3 = rotI<DIR>(t3);
    float2 e1 = cadd(t1, rt3), e3 = csub(t1, rt3);
    float2 o0 = cadd(u0, u2), o2 = csub(u0, u2);
    float2 ru3 = rotI<DIR>(u3);
    float2 o1 = cadd(u1, ru3), o3 = csub(u1, ru3);
    float2 w81 = (DIR < 0) ? make_float2(h, -h) : make_float2(h, h);
    float2 w83 = (DIR < 0) ? make_float2(-h, -h) : make_float2(-h, h);
    float2 a0 = o0;
    float2 a1 = cmul(o1, w81);
    float2 a2 = rotI<DIR>(o2);
    float2 a3 = cmul(o3, w83);
    v[0] = cadd(e0, a0); v[4] = csub(e0, a0);
    v[1] = cadd(e1, a1); v[5] = csub(e1, a1);
    v[2] = cadd(e2, a2); v[6] = csub(e2, a2);
    v[3] = cadd(e3, a3); v[7] = csub(e3, a3);
}

// Middle Stockham radix-8 stage (smem -> smem). S = current span (8 or 64).
template <int S, int DIR>
__device__ __forceinline__ void mid_stage(const float* __restrict__ ir, const float* __restrict__ ii,
                                          float* __restrict__ orr, float* __restrict__ oi, int i) {
    float2 v[8];
#pragma unroll
    for (int r = 0; r < 8; r++) {
        int idx = i + NTHREADS * r;
        v[r] = make_float2(ir[PAD(idx)], ii[PAD(idx)]);
    }
    int k = i & (S - 1);
    const int STEP = NTHREADS / S;  // 4096 / (8*S)
#pragma unroll
    for (int r = 1; r < 8; r++) {
        float2 w = d_tw[(r * k * STEP) & (FFT_N - 1)];
        if (DIR > 0) w.y = -w.y;
        v[r] = cmul(v[r], w);
    }
    dft8<DIR>(v);
    int j = ((i & ~(S - 1)) << 3) + k;  // (i/S)*8S + k
#pragma unroll
    for (int q = 0; q < 8; q++) {
        int idx = j + q * S;
        orr[PAD(idx)] = v[q].x;
        oi[PAD(idx)] = v[q].y;
    }
}

__global__ void __launch_bounds__(NTHREADS, 2)
afdf_kernel(const float2* __restrict__ x, const float2* __restrict__ A,
            const float2* __restrict__ D, float2* __restrict__ out) {
    extern __shared__ float smem[];
    float* b0r = smem;
    float* b0i = smem + PADSTRIDE;
    float* b1r = smem + 2 * PADSTRIDE;
    float* b1i = smem + 3 * PADSTRIDE;

    const int i = threadIdx.x;
    const size_t row = blockIdx.x;
    const float2* __restrict__ xr = x + row * FFT_N;
    float2* __restrict__ outr = out + row * FFT_N;

    float2 v[8];

    // ---- Forward stage 0 (S=1, twiddles = 1) fused with gmem load + A scale ----
#pragma unroll
    for (int r = 0; r < 8; r++) {
        int c = i + NTHREADS * r;
        float2 xv = xr[c];
        float2 a = A[c];
        v[r] = make_float2(a.x * xv.x, a.y * xv.y);  // elementwise re/im scale
    }
    dft8<-1>(v);
#pragma unroll
    for (int q = 0; q < 8; q++) {
        int idx = 8 * i + q;
        b0r[PAD(idx)] = v[q].x;
        b0i[PAD(idx)] = v[q].y;
    }
    __syncthreads();

    mid_stage<8, -1>(b0r, b0i, b1r, b1i, i);
    __syncthreads();
    mid_stage<64, -1>(b1r, b1i, b0r, b0i, i);
    __syncthreads();

    // ---- Forward stage 3 (S=512) + D scale + inverse stage 0, fully in registers ----
#pragma unroll
    for (int r = 0; r < 8; r++) {
        int idx = i + NTHREADS * r;
        v[r] = make_float2(b0r[PAD(idx)], b0i[PAD(idx)]);
    }
#pragma unroll
    for (int r = 1; r < 8; r++) {
        float2 w = d_tw[(r * i) & (FFT_N - 1)];  // k = i, STEP = 1
        v[r] = cmul(v[r], w);
    }
    dft8<-1>(v);
    // Now v[q] = F[i + 512*q] (natural frequency order). Apply D (re/im independent) + 1/N.
    const float invN = 1.0f / (float)FFT_N;
#pragma unroll
    for (int q = 0; q < 8; q++) {
        float2 d = D[i + NTHREADS * q];
        v[q] = make_float2(d.x * v[q].x * invN, d.y * v[q].y * invN);
    }
    // Inverse stage 0 (S=1): inputs needed are f[i + 512*r] — exactly what we hold.
    dft8<1>(v);
#pragma unroll
    for (int q = 0; q < 8; q++) {
        int idx = 8 * i + q;
        b1r[PAD(idx)] = v[q].x;
        b1i[PAD(idx)] = v[q].y;
    }
    __syncthreads();

    mid_stage<8, 1>(b1r, b1i, b0r, b0i, i);
    __syncthreads();
    mid_stage<64, 1>(b0r, b0i, b1r, b1i, i);
    __syncthreads();

    // ---- Inverse stage 3 (S=512), write result straight to gmem ----
#pragma unroll
    for (int r = 0; r < 8; r++) {
        int idx = i + NTHREADS * r;
        v[r] = make_float2(b1r[PAD(idx)], b1i[PAD(idx)]);
    }
#pragma unroll
    for (int r = 1; r < 8; r++) {
        float2 w = d_tw[(r * i) & (FFT_N - 1)];
        w.y = -w.y;  // conjugate for inverse
        v[r] = cmul(v[r], w);
    }
    dft8<1>(v);
#pragma unroll
    for (int q = 0; q < 8; q++) {
        outr[i + NTHREADS * q] = v[q];  // out[n], n = i + 512*q
    }
}

extern "C" void kernel_launch(void* const* d_in, const int* in_sizes, int n_in,
                              void* d_out, int out_size) {
    const float2* x = (const float2*)d_in[0];
    const float2* A = (const float2*)d_in[1];
    const float2* D = (const float2*)d_in[2];
    float2* out = (float2*)d_out;

    // Rebuild twiddle table every launch (deterministic, graph-capturable, ~4K threads).
    tw_init_kernel<<<4, 1024>>>();

    const int smem_bytes = 4 * PADSTRIDE * sizeof(float);  // 67584 B
    cudaFuncSetAttribute(afdf_kernel, cudaFuncAttributeMaxDynamicSharedMemorySize, smem_bytes);
    afdf_kernel<<<8192, NTHREADS, smem_bytes>>>(x, A, D, out);
}

// round 2
// speedup vs baseline: 3.6767x; 3.6767x over previous
#include <cuda_runtime.h>
#include <math.h>

#define FFT_N  4096
#define NT     256
#define PAD(i) ((i) + ((i) >> 4))
#define SMEM_F2 (FFT_N + (FFT_N >> 4))   // 4352 float2 = 34816 B

__device__ __forceinline__ float2 cadd(float2 a, float2 b) { return make_float2(a.x + b.x, a.y + b.y); }
__device__ __forceinline__ float2 csub(float2 a, float2 b) { return make_float2(a.x - b.x, a.y - b.y); }
__device__ __forceinline__ float2 cmul(float2 a, float2 b) {
    return make_float2(fmaf(a.x, b.x, -a.y * b.y), fmaf(a.x, b.y, a.y * b.x));
}
// multiply by -i (DIR=-1, forward) or +i (DIR=+1, inverse)
template <int DIR>
__device__ __forceinline__ float2 rotI(float2 z) {
    return (DIR < 0) ? make_float2(z.y, -z.x) : make_float2(-z.y, z.x);
}
// multiply by the FORWARD constant (cr, ci_fwd); inverse uses conjugate
template <int DIR>
__device__ __forceinline__ float2 cmulc(float2 z, float cr, float ci_fwd) {
    float ci = (DIR < 0) ? ci_fwd : -ci_fwd;
    return cmul(z, make_float2(cr, ci));
}

template <int DIR>
__device__ __forceinline__ void dft4(float2& a, float2& b, float2& c, float2& d) {
    float2 t0 = cadd(a, c), t1 = csub(a, c);
    float2 t2 = cadd(b, d), t3 = rotI<DIR>(csub(b, d));
    a = cadd(t0, t2);
    b = cadd(t1, t3);
    c = csub(t0, t2);
    d = csub(t1, t3);
}

// 16-point DFT as 4x4. Input v[n] natural time order.
// Output X[k1 + 4*k2] lands at v[4*k1 + k2]  -> use OUT(q) when storing.
#define OUT(q) ((((q) & 3) << 2) | ((q) >> 2))

template <int DIR>
__device__ __forceinline__ void dft16(float2 v[16]) {
    const float C1 = 0.92387953251128675613f;   // cos(pi/8)
    const float S1 = 0.38268343236508977173f;   // sin(pi/8)
    const float H  = 0.70710678118654752440f;
    // step 1: DFT4 over n2 for each n1 (stride-4 groups)
    dft4<DIR>(v[0], v[4], v[8],  v[12]);
    dft4<DIR>(v[1], v[5], v[9],  v[13]);
    dft4<DIR>(v[2], v[6], v[10], v[14]);
    dft4<DIR>(v[3], v[7], v[11], v[15]);
    // step 2: twiddle v[n1 + 4*k1] by W16^{n1*k1} (forward values; DIR handles conj)
    v[5]  = cmulc<DIR>(v[5],  C1, -S1);  // W^1
    v[6]  = cmulc<DIR>(v[6],  H,  -H );  // W^2
    v[7]  = cmulc<DIR>(v[7],  S1, -C1);  // W^3
    v[9]  = cmulc<DIR>(v[9],  H,  -H );  // W^2
    v[10] = rotI<DIR>(v[10]);            // W^4
    v[11] = cmulc<DIR>(v[11], -H, -H );  // W^6
    v[13] = cmulc<DIR>(v[13], S1, -C1);  // W^3
    v[14] = cmulc<DIR>(v[14], -H, -H );  // W^6
    v[15] = cmulc<DIR>(v[15], -C1, S1);  // W^9
    // step 3: DFT4 over n1 for each k1 (consecutive groups of 4)
    dft4<DIR>(v[0],  v[1],  v[2],  v[3]);
    dft4<DIR>(v[4],  v[5],  v[6],  v[7]);
    dft4<DIR>(v[8],  v[9],  v[10], v[11]);
    dft4<DIR>(v[12], v[13], v[14], v[15]);
}

// Apply computed twiddle ladder: v[r] *= w1^r for r=1..15
__device__ __forceinline__ void twiddle_ladder(float2 v[16], float theta) {
    float sw, cw;
    __sincosf(theta, &sw, &cw);
    float2 w1 = make_float2(cw, sw);
    float2 w = w1;
    v[1] = cmul(v[1], w);
#pragma unroll
    for (int r = 2; r < 16; r++) {
        w = cmul(w, w1);
        v[r] = cmul(v[r], w);
    }
}

// Middle Stockham radix-16 stage, in-place smem (read-all / sync / write-all / sync)
template <int S, int DIR>
__device__ __forceinline__ void mid_stage(float2* sm, int i) {
    float2 v[16];
#pragma unroll
    for (int r = 0; r < 16; r++) v[r] = sm[PAD(i + NT * r)];
    int k = i & (S - 1);
    // twiddle: W_{16S}^{r*k}  -> angle per step = -/+ 2*pi*k/(16*S)
    float theta = ((DIR < 0) ? -6.283185307179586f : 6.283185307179586f)
                  * (float)k / (float)(16 * S);
    twiddle_ladder(v, theta);
    dft16<DIR>(v);
    __syncthreads();
    int j = ((i & ~(S - 1)) << 4) + k;   // (i/S)*16S + k
#pragma unroll
    for (int q = 0; q < 16; q++) sm[PAD(j + q * S)] = v[OUT(q)];
    __syncthreads();
}

extern __shared__ float2 sm[];

__global__ void __launch_bounds__(NT, 3)
afdf16_kernel(const float2* __restrict__ x, const float2* __restrict__ A,
              const float2* __restrict__ D, float2* __restrict__ out) {
    const int i = threadIdx.x;
    const size_t row = blockIdx.x;
    const float2* __restrict__ xr = x + row * FFT_N;

    // ---- fwd stage 0 (S=1, twiddle-free) fused with gmem load + A scale ----
    {
        float2 v[16];
#pragma unroll
        for (int r = 0; r < 16; r++) {
            int c = i + NT * r;
            float2 xv = xr[c];
            float2 a = A[c];
            v[r] = make_float2(a.x * xv.x, a.y * xv.y);  // independent re/im scale
        }
        dft16<-1>(v);
#pragma unroll
        for (int q = 0; q < 16; q++) sm[PAD(16 * i + q)] = v[OUT(q)];
    }
    __syncthreads();

    // ---- fwd stage 1 (S=16) ----
    mid_stage<16, -1>(sm, i);

    // ---- fwd stage 2 (S=256) + D-scale + inv stage 0, all in registers ----
    {
        float2 u[16];
#pragma unroll
        for (int r = 0; r < 16; r++) u[r] = sm[PAD(i + NT * r)];
        twiddle_ladder(u, -6.283185307179586f * (float)i / (float)FFT_N);
        dft16<-1>(u);
        // u[OUT(q)] = F[i + 256*q] (natural frequency order)
        const float invN = 1.0f / (float)FFT_N;
        float2 g[16];
#pragma unroll
        for (int r = 0; r < 16; r++) {
            float2 fv = u[OUT(r)];
            float2 d = D[i + NT * r];
            g[r] = make_float2(d.x * fv.x * invN, d.y * fv.y * invN);
        }
        // inverse stage 0 (S=1): needs f[i + 256*r] — exactly g[r]
        dft16<1>(g);
        __syncthreads();
#pragma unroll
        for (int q = 0; q < 16; q++) sm[PAD(16 * i + q)] = g[OUT(q)];
    }
    __syncthreads();

    // ---- inv stage 1 (S=16) ----
    mid_stage<16, 1>(sm, i);

    // ---- inv stage 2 (S=256), write straight to gmem ----
    {
        float2 u[16];
#pragma unroll
        for (int r = 0; r < 16; r++) u[r] = sm[PAD(i + NT * r)];
        twiddle_ladder(u, 6.283185307179586f * (float)i / (float)FFT_N);
        dft16<1>(u);
        float2* __restrict__ outr = out + row * FFT_N;
#pragma unroll
        for (int q = 0; q < 16; q++) outr[i + NT * q] = u[OUT(q)];
    }
}

extern "C" void kernel_launch(void* const* d_in, const int* in_sizes, int n_in,
                              void* d_out, int out_size) {
    const float2* x = (const float2*)d_in[0];
    const float2* A = (const float2*)d_in[1];
    const float2* D = (const float2*)d_in[2];
    float2* out = (float2*)d_out;

    int rows = in_sizes[0] / (FFT_N * 2);   // (B, C, 2) float32 -> B rows

    const int smem_bytes = SMEM_F2 * sizeof(float2);  // 34816 B
    cudaFuncSetAttribute(afdf16_kernel, cudaFuncAttributeMaxDynamicSharedMemorySize, smem_bytes);
    afdf16_kernel<<<rows, NT, smem_bytes>>>(x, A, D, out);
}